// round 13
// baseline (speedup 1.0000x reference)
#include <cuda_runtime.h>
#include <math.h>

#define NBATCH 16
#define NANCH  3
#define FS     64
#define NPIX   4096
#define NLAB   50
#define NCLS   80
#define NCH    85
#define CONVBLK 256                 // conv blocks FIRST: blockIdx 0..255
#define CLSBLK (NBATCH*NLAB)        // 800 class-loss blocks after
#define TOTBLK (CONVBLK + CLSBLK)   // 1056
#define CHS    8                    // channels per cp.async stage
#define NSTG   32                   // 256 / CHS stages
#define NBUF   3                    // triple buffer

// ---------------- device scratch ----------------
__device__ float4 g_part[TOTBLK];   // per-block partials: x=xy y=wh z=obj w=cls

__constant__ float c_RW[9] = {1.25f,2.0f,4.125f,3.75f,7.75f,7.375f,14.5f,19.5f,46.625f};
__constant__ float c_RH[9] = {1.625f,3.75f,2.875f,7.625f,5.625f,14.875f,11.25f,24.75f,40.75f};

__device__ __forceinline__ float sigm(float x){ return 1.0f/(1.0f + expf(-x)); }

// softplus(o) = max(o,0)+log1p(exp(-|o|));  BCE(sigmoid(o),t) = sp(o) - t*o
__device__ __forceinline__ float sp(float o){
    return fmaxf(o, 0.0f) + log1pf(expf(-fabsf(o)));
}

__device__ __forceinline__ float warpsum(float v){
    #pragma unroll
    for (int o = 16; o; o >>= 1) v += __shfl_down_sync(0xffffffffu, v, o);
    return v;
}

// packed fp32x2 helpers (Blackwell)
__device__ __forceinline__ unsigned long long packff(float a, float b){
    unsigned long long r;
    asm("mov.b64 %0, {%1, %2};" : "=l"(r) : "r"(__float_as_uint(a)), "r"(__float_as_uint(b)));
    return r;
}
__device__ __forceinline__ void unpackff(unsigned long long v, float& a, float& b){
    unsigned int lo, hi;
    asm("mov.b64 {%0, %1}, %2;" : "=r"(lo), "=r"(hi) : "l"(v));
    a = __uint_as_float(lo); b = __uint_as_float(hi);
}
__device__ __forceinline__ void fma2(unsigned long long& acc,
                                     unsigned long long a, unsigned long long b){
    asm("fma.rn.f32x2 %0, %1, %2, %0;" : "+l"(acc) : "l"(a), "l"(b));
}

// cp.async helpers (Ampere+)
__device__ __forceinline__ void cpa16(unsigned int saddr, const float* g){
    asm volatile("cp.async.cg.shared.global [%0], [%1], 16;" :: "r"(saddr), "l"(g));
}
__device__ __forceinline__ void cpcommit(){ asm volatile("cp.async.commit_group;" ::: "memory"); }
template<int N> __device__ __forceinline__ void cpwait(){
    asm volatile("cp.async.wait_group %0;" :: "n"(N) : "memory");
}

// one channel's contribution: broadcast x against 16 weights (8 packed FMA2)
__device__ __forceinline__ void chan_fma(unsigned long long* accd,
                                         const ulonglong2* W2, int c, float x){
    unsigned long long xd = packff(x, x);
    ulonglong2 q0 = W2[c*4+0], q1 = W2[c*4+1];
    ulonglong2 q2 = W2[c*4+2], q3 = W2[c*4+3];
    fma2(accd[0], xd, q0.x); fma2(accd[1], xd, q0.y);
    fma2(accd[2], xd, q1.x); fma2(accd[3], xd, q1.y);
    fma2(accd[4], xd, q2.x); fma2(accd[5], xd, q2.y);
    fma2(accd[6], xd, q3.x); fma2(accd[7], xd, q3.y);
}

// candidate cell index for one label (or -1)
__device__ __forceinline__ int label_idx(const float* __restrict__ L,
                                         float& tx, float& ty, float& tw, float& th,
                                         int& bi){
    float cls = L[0], x = L[1], y = L[2], w = L[3], h = L[4];
    tx = x*FS; ty = y*FS; tw = w*FS; th = h*FS;
    float best = -1e30f; bi = 0;
    #pragma unroll
    for (int n = 0; n < 9; n++){
        float inter = fminf(tw, c_RW[n]) * fminf(th, c_RH[n]);
        float uni   = tw*th + c_RW[n]*c_RH[n] - inter;
        float iou   = inter/uni;
        if (iou > best){ best = iou; bi = n; }
    }
    bool valid = (cls + x + y + w + h) > 0.0f;
    if (!(valid && bi < NANCH)) return -1;
    int ti = (int)tx, tj = (int)ty;
    return (bi<<12)|(tj<<6)|ti;
}

// ---------------- fused kernel: 256 conv blocks then 800 cls blocks ----------------
__global__ __launch_bounds__(256, 4) void k_fused(const float* __restrict__ xin,
                                                  const float* __restrict__ labels,
                                                  const float* __restrict__ conv_w,
                                                  const float* __restrict__ conv_b){
    int tid = threadIdx.x;

    if (blockIdx.x >= CONVBLK){
        // ================= class-loss block for label (b, k) =================
        int mb = (int)blockIdx.x - CONVBLK;
        int b  = mb / NLAB, k = mb - b*NLAB;

        __shared__ int   s_idx[NLAB];
        __shared__ int   s_win;
        __shared__ float xs[256];
        __shared__ float s_wred[8];

        if (tid < NLAB){
            float tx,ty,tw,th; int bi;
            s_idx[tid] = label_idx(labels + (size_t)(b*NLAB + tid)*5, tx,ty,tw,th, bi);
        }
        __syncthreads();
        if (tid == 0){
            int idx = s_idx[k];
            if (idx >= 0)
                for (int j = k+1; j < NLAB; j++) if (s_idx[j] == idx) { idx = -1; break; }
            s_win = idx;
        }
        __syncthreads();
        int idx = s_win;
        if (idx < 0){
            if (tid == 0) g_part[blockIdx.x] = make_float4(0.f,0.f,0.f,0.f);
            return;
        }
        int a = idx >> 12, pix = idx & 4095;
        int cls = (int)labels[(size_t)(b*NLAB + k)*5];

        xs[tid] = __ldg(xin + ((size_t)(b*256 + tid))*NPIX + pix);
        __syncthreads();

        int w = tid >> 5, lane = tid & 31;   // 8 warps x 10 classes = 80
        float lc = 0.0f;
        #pragma unroll 2
        for (int t = 0; t < 10; t++){
            int c = w + (t<<3);
            int o = a*NCH + 5 + c;
            const float* wr = conv_w + (size_t)o*256;
            float s = 0.0f;
            #pragma unroll
            for (int i = 0; i < 8; i++) s += xs[lane + (i<<5)]*__ldg(wr + lane + (i<<5));
            s = warpsum(s);
            if (lane == 0){
                s += conv_b[o];
                lc += sp(s) - ((c == cls) ? s : 0.0f);
            }
        }
        if (lane == 0) s_wred[w] = lc;
        __syncthreads();
        if (tid == 0){
            float v = 0.0f;
            #pragma unroll
            for (int q = 0; q < 8; q++) v += s_wred[q];
            g_part[blockIdx.x] = make_float4(0.f, 0.f, 0.f, v);
        }
        return;
    }

    // ================= conv + obj/xy/wh block =================
    int cb   = (int)blockIdx.x;
    int b    = cb >> 4;
    int pix0 = (cb & 15) << 8;
    int pix  = pix0 + tid;

    __shared__ __align__(16) float Ws[256*16];          // 16 KB weights (transposed)
    __shared__ __align__(16) float sx[NBUF][CHS*256];   // 3 x 8 KB x-stages
    __shared__ float4 s_tb[NLAB];
    __shared__ float  s_ta[NLAB];
    __shared__ int    s_idx[NLAB];
    __shared__ int    s_fidx[NLAB];
    __shared__ float4 s_l4[NLAB];
    __shared__ float  s_lt[NLAB];
    __shared__ float  s_bias[16];
    __shared__ float  s_red[8][3];

    // base gmem pointer for this block's pixel strip
    const float* xgb = xin + (size_t)b*256*NPIX + pix0;
    unsigned int sxb[NBUF];
    #pragma unroll
    for (int q = 0; q < NBUF; q++)
        sxb[q] = (unsigned int)__cvta_generic_to_shared(&sx[q][0]);

    // issue one 8-channel stage (q-th chunk) into buffer sb: 512 float4, 2/thread
    auto issue_stage = [&](int q, unsigned int sb){
        int i0 = tid, i1 = tid + 256;       // float4 indices within stage
        int c0 = i0 >> 6, o0 = (i0 & 63) << 2;
        int c1 = i1 >> 6, o1 = (i1 & 63) << 2;
        cpa16(sb + (unsigned int)(i0 << 4), xgb + (size_t)(q*CHS + c0)*NPIX + o0);
        cpa16(sb + (unsigned int)(i1 << 4), xgb + (size_t)(q*CHS + c1)*NPIX + o1);
    };

    // prologue: stages 0 and 1 in flight before any setup work
    issue_stage(0, sxb[0]); cpcommit();
    issue_stage(1, sxb[1]); cpcommit();

    for (int i = tid; i < 15*256; i += 256){
        int s = i >> 8, c = i & 255;
        int a = s/5, j = s - a*5;
        Ws[c*16 + s] = conv_w[(a*NCH + j)*256 + c];
    }
    Ws[tid*16 + 15] = 0.0f;
    if (tid >= 224 && tid < 239){ int s = tid-224; int a = s/5; s_bias[s] = conv_b[a*NCH + (s - a*5)]; }
    if (tid == 239) s_bias[15] = 0.0f;
    if (tid < NLAB){
        const float* L = labels + (size_t)(b*NLAB + tid)*5;
        float tx,ty,tw,th; int bi;
        int idx = label_idx(L, tx,ty,tw,th, bi);
        s_idx[tid] = idx;
        s_tb[tid]  = make_float4(tx - tw*0.5f, ty - th*0.5f, tx + tw*0.5f, ty + th*0.5f);
        s_ta[tid]  = tw*th;
        int ti = (int)tx, tj = (int)ty;
        int sb = (bi < NANCH) ? bi : 0;
        s_l4[tid] = make_float4(tx - (float)ti, ty - (float)tj,
                                logf(tw / c_RW[sb] + 1e-16f),
                                logf(th / c_RH[sb] + 1e-16f));
        s_lt[tid] = 2.0f - tw*th*(1.0f/(float)(FS*FS));
    }
    __syncthreads();

    // parallel last-wins winner selection
    if (tid < NLAB){
        int idx = s_idx[tid];
        if (idx >= 0)
            for (int j = tid+1; j < NLAB; j++) if (s_idx[j] == idx) { idx = -1; break; }
        s_fidx[tid] = idx;
    }

    unsigned long long accd[8];
    #pragma unroll
    for (int p = 0; p < 8; p++) accd[p] = packff(s_bias[2*p], s_bias[2*p+1]);

    const ulonglong2* W2 = reinterpret_cast<const ulonglong2*>(Ws);

    // pipeline, ONE barrier per stage:
    //   wait stage s; barrier; issue stage s+2 into buf[(s+2)%3] (its previous
    //   reader was stage s-1, whose compute finished before this barrier);
    //   compute stage s from buf[s%3].
    #pragma unroll 1
    for (int s = 0; s < NSTG; s++){
        if (s < NSTG-1) cpwait<1>(); else cpwait<0>();
        __syncthreads();                        // stage s visible; buf reuse safe
        if (s + 2 < NSTG){
            issue_stage(s + 2, sxb[(s + 2) % NBUF]);
            cpcommit();
        }
        const float* xb = sx[s % NBUF];
        #pragma unroll
        for (int i = 0; i < CHS; i++)
            chan_fma(accd, W2, s*CHS + i, xb[i*256 + tid]);
    }

    float acc[16];
    #pragma unroll
    for (int p = 0; p < 8; p++) unpackff(accd[p], acc[2*p], acc[2*p+1]);

    const float MAW[3] = {1.25f, 2.0f, 4.125f};
    const float MAH[3] = {1.625f, 3.75f, 2.875f};
    float fw = (float)(pix & 63);
    float fh = (float)(pix >> 6);
    float ax0[3], ay0[3], ax1[3], ay1[3], areaA[3];
    #pragma unroll
    for (int a = 0; a < 3; a++){
        float o0 = acc[a*5+0], o1 = acc[a*5+1];
        float o2 = acc[a*5+2], o3 = acc[a*5+3];
        float pw = expf(o2)*MAW[a], ph = expf(o3)*MAH[a];
        float px = sigm(o0) + fw, py = sigm(o1) + fh;
        areaA[a] = pw*ph;
        ax0[a] = px - pw*0.5f; ay0[a] = py - ph*0.5f;
        ax1[a] = px + pw*0.5f; ay1[a] = py + ph*0.5f;
    }

    int ign = 0;
    int msl[3] = {-1,-1,-1};
    for (int kk = 0; kk < NLAB; kk++){
        float4 t = s_tb[kk];
        float ta = s_ta[kk];
        #pragma unroll
        for (int a = 0; a < 3; a++){
            float iw = fmaxf(fminf(ax1[a], t.z) - fmaxf(ax0[a], t.x), 0.0f);
            float ih = fmaxf(fminf(ay1[a], t.w) - fmaxf(ay0[a], t.y), 0.0f);
            float inter = iw*ih;
            float den   = areaA[a] + ta - inter;
            ign |= (inter > 0.7f*den) << a;
        }
        int e = s_fidx[kk];
        if (e >= 0 && (e & 4095) == pix) msl[e >> 12] = kk;
    }

    float lobj = 0.0f, lxy = 0.0f, lwh = 0.0f;
    #pragma unroll
    for (int a = 0; a < 3; a++){
        float o4 = acc[a*5+4];
        int slot = msl[a];
        if (slot >= 0){
            lobj += sp(o4) - o4;
            float4 d = s_l4[slot];
            float ts = s_lt[slot];
            float o0 = acc[a*5+0], o1 = acc[a*5+1];
            lxy += (sp(o0) - d.x*o0 + sp(o1) - d.y*o1)*ts;
            float dw = acc[a*5+2] - d.z, dh = acc[a*5+3] - d.w;
            lwh += (dw*dw + dh*dh)*0.5f*ts;
        } else if (!((ign >> a) & 1)){
            lobj += sp(o4);
        }
    }

    lxy = warpsum(lxy); lwh = warpsum(lwh); lobj = warpsum(lobj);
    int wid = tid >> 5, lane = tid & 31;
    if (lane == 0){ s_red[wid][0] = lxy; s_red[wid][1] = lwh; s_red[wid][2] = lobj; }
    __syncthreads();
    if (tid == 0){
        float vx=0.f, vw=0.f, vo=0.f;
        #pragma unroll
        for (int q = 0; q < 8; q++){ vx += s_red[q][0]; vw += s_red[q][1]; vo += s_red[q][2]; }
        g_part[blockIdx.x] = make_float4(vx, vw, vo, 0.f);
    }
}

// ---------------- finalize: reduce per-block partials ----------------
__global__ __launch_bounds__(128) void k_final(float* __restrict__ out){
    int w = threadIdx.x >> 5, lane = threadIdx.x & 31;
    const float* P = (const float*)g_part;
    double s = 0.0;
    for (int i = lane; i < TOTBLK; i += 32) s += (double)P[i*4 + w];
    #pragma unroll
    for (int o = 16; o; o >>= 1) s += __shfl_down_sync(0xffffffffu, s, o);
    __shared__ double sr[4];
    if (lane == 0) sr[w] = s;
    __syncthreads();
    if (threadIdx.x == 0){
        double xy = sr[0], wh = sr[1], obj = sr[2], cls = sr[3];
        out[0] = (float)(xy + wh + obj + cls);
        out[1] = (float)xy;
        out[2] = (float)wh;
        out[3] = (float)obj;
        out[4] = (float)cls;
    }
}

extern "C" void kernel_launch(void* const* d_in, const int* in_sizes, int n_in,
                              void* d_out, int out_size){
    const float* xin    = (const float*)d_in[0];
    const float* labels = (const float*)d_in[1];
    const float* conv_w = (const float*)d_in[2];
    const float* conv_b = (const float*)d_in[3];
    float* out = (float*)d_out;

    k_fused<<<TOTBLK, 256>>>(xin, labels, conv_w, conv_b);
    k_final<<<1, 128>>>(out);
}

// round 14
// speedup vs baseline: 1.0736x; 1.0736x over previous
#include <cuda_runtime.h>
#include <math.h>

#define NBATCH 16
#define NANCH  3
#define FS     64
#define NPIX   4096
#define NLAB   50
#define NCLS   80
#define NCH    85
#define CONVBLK 128                 // conv blocks FIRST: 512 px each, 2 px/thread
#define CLSBLK (NBATCH*NLAB)        // 800 class-loss blocks after
#define TOTBLK (CONVBLK + CLSBLK)   // 928

// ---------------- device scratch ----------------
__device__ float4 g_part[TOTBLK];   // per-block partials: x=xy y=wh z=obj w=cls

__constant__ float c_RW[9] = {1.25f,2.0f,4.125f,3.75f,7.75f,7.375f,14.5f,19.5f,46.625f};
__constant__ float c_RH[9] = {1.625f,3.75f,2.875f,7.625f,5.625f,14.875f,11.25f,24.75f,40.75f};

__device__ __forceinline__ float sigm(float x){ return 1.0f/(1.0f + expf(-x)); }

// softplus(o) = max(o,0)+log1p(exp(-|o|));  BCE(sigmoid(o),t) = sp(o) - t*o
__device__ __forceinline__ float sp(float o){
    return fmaxf(o, 0.0f) + log1pf(expf(-fabsf(o)));
}

__device__ __forceinline__ float warpsum(float v){
    #pragma unroll
    for (int o = 16; o; o >>= 1) v += __shfl_down_sync(0xffffffffu, v, o);
    return v;
}

// packed fp32x2 helpers (Blackwell)
__device__ __forceinline__ unsigned long long packff(float a, float b){
    unsigned long long r;
    asm("mov.b64 %0, {%1, %2};" : "=l"(r) : "r"(__float_as_uint(a)), "r"(__float_as_uint(b)));
    return r;
}
__device__ __forceinline__ void unpackff(unsigned long long v, float& a, float& b){
    unsigned int lo, hi;
    asm("mov.b64 {%0, %1}, %2;" : "=r"(lo), "=r"(hi) : "l"(v));
    a = __uint_as_float(lo); b = __uint_as_float(hi);
}
__device__ __forceinline__ void fma2(unsigned long long& acc,
                                     unsigned long long a, unsigned long long b){
    asm("fma.rn.f32x2 %0, %1, %2, %0;" : "+l"(acc) : "l"(a), "l"(b));
}

// one channel, TWO pixels: weights loaded once, 16 packed FMA2
__device__ __forceinline__ void chan2(unsigned long long* A, unsigned long long* B,
                                      const ulonglong2* W2, int c, float2 x2){
    unsigned long long xa = packff(x2.x, x2.x);
    unsigned long long xb = packff(x2.y, x2.y);
    ulonglong2 q0 = W2[c*4+0], q1 = W2[c*4+1];
    ulonglong2 q2 = W2[c*4+2], q3 = W2[c*4+3];
    fma2(A[0], xa, q0.x); fma2(B[0], xb, q0.x);
    fma2(A[1], xa, q0.y); fma2(B[1], xb, q0.y);
    fma2(A[2], xa, q1.x); fma2(B[2], xb, q1.x);
    fma2(A[3], xa, q1.y); fma2(B[3], xb, q1.y);
    fma2(A[4], xa, q2.x); fma2(B[4], xb, q2.x);
    fma2(A[5], xa, q2.y); fma2(B[5], xb, q2.y);
    fma2(A[6], xa, q3.x); fma2(B[6], xb, q3.x);
    fma2(A[7], xa, q3.y); fma2(B[7], xb, q3.y);
}

// candidate cell index for one label (or -1)
__device__ __forceinline__ int label_idx(const float* __restrict__ L,
                                         float& tx, float& ty, float& tw, float& th,
                                         int& bi){
    float cls = L[0], x = L[1], y = L[2], w = L[3], h = L[4];
    tx = x*FS; ty = y*FS; tw = w*FS; th = h*FS;
    float best = -1e30f; bi = 0;
    #pragma unroll
    for (int n = 0; n < 9; n++){
        float inter = fminf(tw, c_RW[n]) * fminf(th, c_RH[n]);
        float uni   = tw*th + c_RW[n]*c_RH[n] - inter;
        float iou   = inter/uni;
        if (iou > best){ best = iou; bi = n; }
    }
    bool valid = (cls + x + y + w + h) > 0.0f;
    if (!(valid && bi < NANCH)) return -1;
    int ti = (int)tx, tj = (int)ty;
    return (bi<<12)|(tj<<6)|ti;
}

// per-pixel epilogue: ignore-IoU + losses for the 3 anchors at pixel p
__device__ __forceinline__ void pixel_losses(
    const float* acc, int p,
    const float4* s_tb, const float* s_ta, const int* s_fidx,
    const float4* s_l4, const float* s_lt,
    float& lxy, float& lwh, float& lobj)
{
    const float MAW[3] = {1.25f, 2.0f, 4.125f};
    const float MAH[3] = {1.625f, 3.75f, 2.875f};
    float fw = (float)(p & 63);
    float fh = (float)(p >> 6);
    float ax0[3], ay0[3], ax1[3], ay1[3], areaA[3];
    #pragma unroll
    for (int a = 0; a < 3; a++){
        float o0 = acc[a*5+0], o1 = acc[a*5+1];
        float o2 = acc[a*5+2], o3 = acc[a*5+3];
        float pw = expf(o2)*MAW[a], ph = expf(o3)*MAH[a];
        float px = sigm(o0) + fw, py = sigm(o1) + fh;
        areaA[a] = pw*ph;
        ax0[a] = px - pw*0.5f; ay0[a] = py - ph*0.5f;
        ax1[a] = px + pw*0.5f; ay1[a] = py + ph*0.5f;
    }
    int ign = 0;
    int msl[3] = {-1,-1,-1};
    for (int kk = 0; kk < NLAB; kk++){
        float4 t = s_tb[kk];
        float ta = s_ta[kk];
        #pragma unroll
        for (int a = 0; a < 3; a++){
            float iw = fmaxf(fminf(ax1[a], t.z) - fmaxf(ax0[a], t.x), 0.0f);
            float ih = fmaxf(fminf(ay1[a], t.w) - fmaxf(ay0[a], t.y), 0.0f);
            float inter = iw*ih;
            float den   = areaA[a] + ta - inter;
            ign |= (inter > 0.7f*den) << a;
        }
        int e = s_fidx[kk];
        if (e >= 0 && (e & 4095) == p) msl[e >> 12] = kk;
    }
    #pragma unroll
    for (int a = 0; a < 3; a++){
        float o4 = acc[a*5+4];
        int slot = msl[a];
        if (slot >= 0){
            lobj += sp(o4) - o4;
            float4 d = s_l4[slot];
            float ts = s_lt[slot];
            float o0 = acc[a*5+0], o1 = acc[a*5+1];
            lxy += (sp(o0) - d.x*o0 + sp(o1) - d.y*o1)*ts;
            float dw = acc[a*5+2] - d.z, dh = acc[a*5+3] - d.w;
            lwh += (dw*dw + dh*dh)*0.5f*ts;
        } else if (!((ign >> a) & 1)){
            lobj += sp(o4);
        }
    }
}

// ---------------- fused kernel: 128 conv blocks then 800 cls blocks ----------------
__global__ __launch_bounds__(256, 3) void k_fused(const float* __restrict__ xin,
                                                  const float* __restrict__ labels,
                                                  const float* __restrict__ conv_w,
                                                  const float* __restrict__ conv_b){
    int tid = threadIdx.x;

    if (blockIdx.x >= CONVBLK){
        // ================= class-loss block for label (b, k) =================
        int mb = (int)blockIdx.x - CONVBLK;
        int b  = mb / NLAB, k = mb - b*NLAB;

        __shared__ int   s_idx[NLAB];
        __shared__ int   s_win;
        __shared__ float xs[256];
        __shared__ float s_wred[8];

        if (tid < NLAB){
            float tx,ty,tw,th; int bi;
            s_idx[tid] = label_idx(labels + (size_t)(b*NLAB + tid)*5, tx,ty,tw,th, bi);
        }
        __syncthreads();
        if (tid == 0){
            int idx = s_idx[k];
            if (idx >= 0)
                for (int j = k+1; j < NLAB; j++) if (s_idx[j] == idx) { idx = -1; break; }
            s_win = idx;
        }
        __syncthreads();
        int idx = s_win;
        if (idx < 0){
            if (tid == 0) g_part[blockIdx.x] = make_float4(0.f,0.f,0.f,0.f);
            return;
        }
        int a = idx >> 12, pix = idx & 4095;
        int cls = (int)labels[(size_t)(b*NLAB + k)*5];

        xs[tid] = __ldg(xin + ((size_t)(b*256 + tid))*NPIX + pix);
        __syncthreads();

        int w = tid >> 5, lane = tid & 31;   // 8 warps x 10 classes = 80
        float lc = 0.0f;
        #pragma unroll 2
        for (int t = 0; t < 10; t++){
            int c = w + (t<<3);
            int o = a*NCH + 5 + c;
            const float* wr = conv_w + (size_t)o*256;
            float s = 0.0f;
            #pragma unroll
            for (int i = 0; i < 8; i++) s += xs[lane + (i<<5)]*__ldg(wr + lane + (i<<5));
            s = warpsum(s);
            if (lane == 0){
                s += conv_b[o];
                lc += sp(s) - ((c == cls) ? s : 0.0f);
            }
        }
        if (lane == 0) s_wred[w] = lc;
        __syncthreads();
        if (tid == 0){
            float v = 0.0f;
            #pragma unroll
            for (int q = 0; q < 8; q++) v += s_wred[q];
            g_part[blockIdx.x] = make_float4(0.f, 0.f, 0.f, v);
        }
        return;
    }

    // ================= conv + obj/xy/wh block: 512 px, 2 adjacent px/thread ======
    int cb    = (int)blockIdx.x;
    int b     = cb >> 3;                      // 8 blocks per batch image
    int strip = (cb & 7) << 9;                // 512-pixel strip
    int p0    = strip + 2*tid;                // this thread: pixels p0, p0+1

    __shared__ __align__(16) float Ws[256*16];
    __shared__ float4 s_tb[NLAB];
    __shared__ float  s_ta[NLAB];
    __shared__ int    s_idx[NLAB];
    __shared__ int    s_fidx[NLAB];
    __shared__ float4 s_l4[NLAB];
    __shared__ float  s_lt[NLAB];
    __shared__ float  s_bias[16];
    __shared__ float  s_red[8][3];

    for (int i = tid; i < 15*256; i += 256){
        int s = i >> 8, c = i & 255;
        int a = s/5, j = s - a*5;
        Ws[c*16 + s] = conv_w[(a*NCH + j)*256 + c];
    }
    Ws[tid*16 + 15] = 0.0f;
    if (tid >= 224 && tid < 239){ int s = tid-224; int a = s/5; s_bias[s] = conv_b[a*NCH + (s - a*5)]; }
    if (tid == 239) s_bias[15] = 0.0f;
    if (tid < NLAB){
        const float* L = labels + (size_t)(b*NLAB + tid)*5;
        float tx,ty,tw,th; int bi;
        int idx = label_idx(L, tx,ty,tw,th, bi);
        s_idx[tid] = idx;
        s_tb[tid]  = make_float4(tx - tw*0.5f, ty - th*0.5f, tx + tw*0.5f, ty + th*0.5f);
        s_ta[tid]  = tw*th;
        int ti = (int)tx, tj = (int)ty;
        int sb = (bi < NANCH) ? bi : 0;
        s_l4[tid] = make_float4(tx - (float)ti, ty - (float)tj,
                                logf(tw / c_RW[sb] + 1e-16f),
                                logf(th / c_RH[sb] + 1e-16f));
        s_lt[tid] = 2.0f - tw*th*(1.0f/(float)(FS*FS));
    }
    __syncthreads();

    // parallel last-wins winner selection
    if (tid < NLAB){
        int idx = s_idx[tid];
        if (idx >= 0)
            for (int j = tid+1; j < NLAB; j++) if (s_idx[j] == idx) { idx = -1; break; }
        s_fidx[tid] = idx;
    }

    unsigned long long accA[8], accB[8];
    #pragma unroll
    for (int p = 0; p < 8; p++){
        accA[p] = packff(s_bias[2*p], s_bias[2*p+1]);
        accB[p] = accA[p];
    }

    const float* xp = xin + (size_t)b*256*NPIX + p0;
    const ulonglong2* W2 = reinterpret_cast<const ulonglong2*>(Ws);

    // depth-4 rolling prefetch of float2 (2 adjacent pixels per load)
    float2 xv[4];
    #pragma unroll
    for (int i = 0; i < 4; i++)
        xv[i] = *reinterpret_cast<const float2*>(xp + (size_t)i*NPIX);

    #pragma unroll 1
    for (int c = 0; c < 252; c += 4){
        float2 xn0 = *reinterpret_cast<const float2*>(xp + (size_t)(c+4)*NPIX);
        float2 xn1 = *reinterpret_cast<const float2*>(xp + (size_t)(c+5)*NPIX);
        float2 xn2 = *reinterpret_cast<const float2*>(xp + (size_t)(c+6)*NPIX);
        float2 xn3 = *reinterpret_cast<const float2*>(xp + (size_t)(c+7)*NPIX);
        chan2(accA, accB, W2, c+0, xv[0]);
        chan2(accA, accB, W2, c+1, xv[1]);
        chan2(accA, accB, W2, c+2, xv[2]);
        chan2(accA, accB, W2, c+3, xv[3]);
        xv[0] = xn0; xv[1] = xn1; xv[2] = xn2; xv[3] = xn3;
    }
    #pragma unroll
    for (int i = 0; i < 4; i++) chan2(accA, accB, W2, 252 + i, xv[i]);

    __syncthreads();   // s_fidx visible

    float lxy = 0.0f, lwh = 0.0f, lobj = 0.0f;
    {
        float acc[16];
        #pragma unroll
        for (int p = 0; p < 8; p++) unpackff(accA[p], acc[2*p], acc[2*p+1]);
        pixel_losses(acc, p0, s_tb, s_ta, s_fidx, s_l4, s_lt, lxy, lwh, lobj);
        #pragma unroll
        for (int p = 0; p < 8; p++) unpackff(accB[p], acc[2*p], acc[2*p+1]);
        pixel_losses(acc, p0+1, s_tb, s_ta, s_fidx, s_l4, s_lt, lxy, lwh, lobj);
    }

    lxy = warpsum(lxy); lwh = warpsum(lwh); lobj = warpsum(lobj);
    int wid = tid >> 5, lane = tid & 31;
    if (lane == 0){ s_red[wid][0] = lxy; s_red[wid][1] = lwh; s_red[wid][2] = lobj; }
    __syncthreads();
    if (tid == 0){
        float vx=0.f, vw=0.f, vo=0.f;
        #pragma unroll
        for (int q = 0; q < 8; q++){ vx += s_red[q][0]; vw += s_red[q][1]; vo += s_red[q][2]; }
        g_part[blockIdx.x] = make_float4(vx, vw, vo, 0.f);
    }
}

// ---------------- finalize: reduce per-block partials ----------------
__global__ __launch_bounds__(128) void k_final(float* __restrict__ out){
    int w = threadIdx.x >> 5, lane = threadIdx.x & 31;
    const float* P = (const float*)g_part;
    double s = 0.0;
    for (int i = lane; i < TOTBLK; i += 32) s += (double)P[i*4 + w];
    #pragma unroll
    for (int o = 16; o; o >>= 1) s += __shfl_down_sync(0xffffffffu, s, o);
    __shared__ double sr[4];
    if (lane == 0) sr[w] = s;
    __syncthreads();
    if (threadIdx.x == 0){
        double xy = sr[0], wh = sr[1], obj = sr[2], cls = sr[3];
        out[0] = (float)(xy + wh + obj + cls);
        out[1] = (float)xy;
        out[2] = (float)wh;
        out[3] = (float)obj;
        out[4] = (float)cls;
    }
}

extern "C" void kernel_launch(void* const* d_in, const int* in_sizes, int n_in,
                              void* d_out, int out_size){
    const float* xin    = (const float*)d_in[0];
    const float* labels = (const float*)d_in[1];
    const float* conv_w = (const float*)d_in[2];
    const float* conv_b = (const float*)d_in[3];
    float* out = (float*)d_out;

    k_fused<<<TOTBLK, 256>>>(xin, labels, conv_w, conv_b);
    k_final<<<1, 128>>>(out);
}

// round 15
// speedup vs baseline: 1.4196x; 1.3223x over previous
#include <cuda_runtime.h>
#include <math.h>

#define NBATCH 16
#define NANCH  3
#define FS     64
#define NPIX   4096
#define NLAB   50
#define NCLS   80
#define NCH    85
#define CONVBLK 256                 // conv blocks FIRST: blockIdx 0..255, 256 px each
#define CLSBLK (NBATCH*NLAB)        // 800 class-loss blocks after
#define TOTBLK (CONVBLK + CLSBLK)   // 1056
#define NBUF   3                    // cp.async ring depth
#define XPITCH 264                  // stage pitch (floats): conflict-free A-frag loads
#define PPITCH 17                   // transpose pitch

// ---------------- device scratch ----------------
__device__ float4 g_part[TOTBLK];   // per-block partials: x=xy y=wh z=obj w=cls

__constant__ float c_RW[9] = {1.25f,2.0f,4.125f,3.75f,7.75f,7.375f,14.5f,19.5f,46.625f};
__constant__ float c_RH[9] = {1.625f,3.75f,2.875f,7.625f,5.625f,14.875f,11.25f,24.75f,40.75f};

__device__ __forceinline__ float sigm(float x){ return 1.0f/(1.0f + expf(-x)); }

// softplus(o) = max(o,0)+log1p(exp(-|o|));  BCE(sigmoid(o),t) = sp(o) - t*o
__device__ __forceinline__ float sp(float o){
    return fmaxf(o, 0.0f) + log1pf(expf(-fabsf(o)));
}

__device__ __forceinline__ float warpsum(float v){
    #pragma unroll
    for (int o = 16; o; o >>= 1) v += __shfl_down_sync(0xffffffffu, v, o);
    return v;
}

// tf32 round-to-nearest conversion (result stored as float bit-pattern)
__device__ __forceinline__ float f2tf32(float f){
    unsigned int r;
    asm("cvt.rna.tf32.f32 %0, %1;" : "=r"(r) : "f"(f));
    return __uint_as_float(r);
}

// warp-level tensor-core mma: D(16x8) += A(16x8) * B(8x8), tf32 in, fp32 acc
__device__ __forceinline__ void mma_tf32(float& c0, float& c1, float& c2, float& c3,
                                         unsigned a0, unsigned a1, unsigned a2, unsigned a3,
                                         unsigned b0, unsigned b1){
    asm volatile("mma.sync.aligned.m16n8k8.row.col.f32.tf32.tf32.f32 "
                 "{%0,%1,%2,%3}, {%4,%5,%6,%7}, {%8,%9}, {%0,%1,%2,%3};"
                 : "+f"(c0), "+f"(c1), "+f"(c2), "+f"(c3)
                 : "r"(a0), "r"(a1), "r"(a2), "r"(a3), "r"(b0), "r"(b1));
}

// cp.async helpers (Ampere+)
__device__ __forceinline__ void cpa16(unsigned int saddr, const float* g){
    asm volatile("cp.async.cg.shared.global [%0], [%1], 16;" :: "r"(saddr), "l"(g));
}
__device__ __forceinline__ void cpcommit(){ asm volatile("cp.async.commit_group;" ::: "memory"); }
template<int N> __device__ __forceinline__ void cpwait(){
    asm volatile("cp.async.wait_group %0;" :: "n"(N) : "memory");
}

// candidate cell index for one label (or -1)
__device__ __forceinline__ int label_idx(const float* __restrict__ L,
                                         float& tx, float& ty, float& tw, float& th,
                                         int& bi){
    float cls = L[0], x = L[1], y = L[2], w = L[3], h = L[4];
    tx = x*FS; ty = y*FS; tw = w*FS; th = h*FS;
    float best = -1e30f; bi = 0;
    #pragma unroll
    for (int n = 0; n < 9; n++){
        float inter = fminf(tw, c_RW[n]) * fminf(th, c_RH[n]);
        float uni   = tw*th + c_RW[n]*c_RH[n] - inter;
        float iou   = inter/uni;
        if (iou > best){ best = iou; bi = n; }
    }
    bool valid = (cls + x + y + w + h) > 0.0f;
    if (!(valid && bi < NANCH)) return -1;
    int ti = (int)tx, tj = (int)ty;
    return (bi<<12)|(tj<<6)|ti;
}

// per-pixel epilogue: ignore-IoU + losses for the 3 anchors at pixel p
__device__ __forceinline__ void pixel_losses(
    const float* acc, int p,
    const float4* s_tb, const float* s_ta, const int* s_fidx,
    const float4* s_l4, const float* s_lt,
    float& lxy, float& lwh, float& lobj)
{
    const float MAW[3] = {1.25f, 2.0f, 4.125f};
    const float MAH[3] = {1.625f, 3.75f, 2.875f};
    float fw = (float)(p & 63);
    float fh = (float)(p >> 6);
    float ax0[3], ay0[3], ax1[3], ay1[3], areaA[3];
    #pragma unroll
    for (int a = 0; a < 3; a++){
        float o0 = acc[a*5+0], o1 = acc[a*5+1];
        float o2 = acc[a*5+2], o3 = acc[a*5+3];
        float pw = expf(o2)*MAW[a], ph = expf(o3)*MAH[a];
        float px = sigm(o0) + fw, py = sigm(o1) + fh;
        areaA[a] = pw*ph;
        ax0[a] = px - pw*0.5f; ay0[a] = py - ph*0.5f;
        ax1[a] = px + pw*0.5f; ay1[a] = py + ph*0.5f;
    }
    int ign = 0;
    int msl[3] = {-1,-1,-1};
    for (int kk = 0; kk < NLAB; kk++){
        float4 t = s_tb[kk];
        float ta = s_ta[kk];
        #pragma unroll
        for (int a = 0; a < 3; a++){
            float iw = fmaxf(fminf(ax1[a], t.z) - fmaxf(ax0[a], t.x), 0.0f);
            float ih = fmaxf(fminf(ay1[a], t.w) - fmaxf(ay0[a], t.y), 0.0f);
            float inter = iw*ih;
            float den   = areaA[a] + ta - inter;
            ign |= (inter > 0.7f*den) << a;
        }
        int e = s_fidx[kk];
        if (e >= 0 && (e & 4095) == p) msl[e >> 12] = kk;
    }
    #pragma unroll
    for (int a = 0; a < 3; a++){
        float o4 = acc[a*5+4];
        int slot = msl[a];
        if (slot >= 0){
            lobj += sp(o4) - o4;
            float4 d = s_l4[slot];
            float ts = s_lt[slot];
            float o0 = acc[a*5+0], o1 = acc[a*5+1];
            lxy += (sp(o0) - d.x*o0 + sp(o1) - d.y*o1)*ts;
            float dw = acc[a*5+2] - d.z, dh = acc[a*5+3] - d.w;
            lwh += (dw*dw + dh*dh)*0.5f*ts;
        } else if (!((ign >> a) & 1)){
            lobj += sp(o4);
        }
    }
}

// ---------------- fused kernel: 256 conv (tf32 MMA) + 800 cls blocks ----------------
__global__ __launch_bounds__(256, 4) void k_fused(const float* __restrict__ xin,
                                                  const float* __restrict__ labels,
                                                  const float* __restrict__ conv_w,
                                                  const float* __restrict__ conv_b){
    // shared state common to both branches (Xbuf aliased: stages / transpose / cls xs)
    __shared__ __align__(16) float Xbuf[NBUF*8*XPITCH];   // 25344 B
    __shared__ __align__(16) float WB[256*16];            // tf32 weights [c][s], 16 KB
    __shared__ float4 s_tb[NLAB];
    __shared__ float  s_ta[NLAB];
    __shared__ int    s_idx[NLAB];
    __shared__ int    s_fidx[NLAB];
    __shared__ float4 s_l4[NLAB];
    __shared__ float  s_lt[NLAB];
    __shared__ float  s_bias[16];
    __shared__ float  s_red[8][3];
    __shared__ float  s_wred[8];
    __shared__ int    s_win;

    int tid = threadIdx.x;

    if (blockIdx.x >= CONVBLK){
        // ================= class-loss block for label (b, k) =================
        int mb = (int)blockIdx.x - CONVBLK;
        int b  = mb / NLAB, k = mb - b*NLAB;
        float* xs = Xbuf;

        if (tid < NLAB){
            float tx,ty,tw,th; int bi;
            s_idx[tid] = label_idx(labels + (size_t)(b*NLAB + tid)*5, tx,ty,tw,th, bi);
        }
        __syncthreads();
        if (tid == 0){
            int idx = s_idx[k];
            if (idx >= 0)
                for (int j = k+1; j < NLAB; j++) if (s_idx[j] == idx) { idx = -1; break; }
            s_win = idx;
        }
        __syncthreads();
        int idx = s_win;
        if (idx < 0){
            if (tid == 0) g_part[blockIdx.x] = make_float4(0.f,0.f,0.f,0.f);
            return;
        }
        int a = idx >> 12, pix = idx & 4095;
        int cls = (int)labels[(size_t)(b*NLAB + k)*5];

        xs[tid] = __ldg(xin + ((size_t)(b*256 + tid))*NPIX + pix);
        __syncthreads();

        int w = tid >> 5, lane = tid & 31;   // 8 warps x 10 classes = 80
        float lc = 0.0f;
        #pragma unroll 2
        for (int t = 0; t < 10; t++){
            int c = w + (t<<3);
            int o = a*NCH + 5 + c;
            const float* wr = conv_w + (size_t)o*256;
            float s = 0.0f;
            #pragma unroll
            for (int i = 0; i < 8; i++) s += xs[lane + (i<<5)]*__ldg(wr + lane + (i<<5));
            s = warpsum(s);
            if (lane == 0){
                s += conv_b[o];
                lc += sp(s) - ((c == cls) ? s : 0.0f);
            }
        }
        if (lane == 0) s_wred[w] = lc;
        __syncthreads();
        if (tid == 0){
            float v = 0.0f;
            #pragma unroll
            for (int q = 0; q < 8; q++) v += s_wred[q];
            g_part[blockIdx.x] = make_float4(0.f, 0.f, 0.f, v);
        }
        return;
    }

    // ================= conv block: 256 px, tf32 MMA =================
    int cb   = (int)blockIdx.x;
    int b    = cb >> 4;
    int pix0 = (cb & 15) << 8;

    const float* xgb = xin + (size_t)b*256*NPIX + pix0;
    unsigned int sx0 = (unsigned int)__cvta_generic_to_shared(&Xbuf[0]);

    // stage q (8 channels) -> ring buffer buf; 512 float4, 2 per thread
    auto issue_stage = [&](int q, int buf){
        unsigned int sb = sx0 + (unsigned int)(buf*(8*XPITCH*4));
        int i0 = tid, i1 = tid + 256;
        int c0 = i0 >> 6, p0 = (i0 & 63) << 2;
        int c1 = i1 >> 6, p1 = (i1 & 63) << 2;
        cpa16(sb + (unsigned int)((c0*XPITCH + p0) << 2), xgb + (size_t)(q*8 + c0)*NPIX + p0);
        cpa16(sb + (unsigned int)((c1*XPITCH + p1) << 2), xgb + (size_t)(q*8 + c1)*NPIX + p1);
    };
    issue_stage(0, 0); cpcommit();
    issue_stage(1, 1); cpcommit();

    // weights -> smem as tf32, layout WB[c*16 + s]
    for (int i = tid; i < 15*256; i += 256){
        int s = i >> 8, c = i & 255;
        int a = s/5, j = s - a*5;
        WB[c*16 + s] = f2tf32(conv_w[(a*NCH + j)*256 + c]);
    }
    WB[tid*16 + 15] = 0.0f;
    if (tid >= 224 && tid < 239){ int s = tid-224; int a = s/5; s_bias[s] = conv_b[a*NCH + (s - a*5)]; }
    if (tid == 239) s_bias[15] = 0.0f;
    if (tid < NLAB){
        const float* L = labels + (size_t)(b*NLAB + tid)*5;
        float tx,ty,tw,th; int bi;
        int idx = label_idx(L, tx,ty,tw,th, bi);
        s_idx[tid] = idx;
        s_tb[tid]  = make_float4(tx - tw*0.5f, ty - th*0.5f, tx + tw*0.5f, ty + th*0.5f);
        s_ta[tid]  = tw*th;
        int ti = (int)tx, tj = (int)ty;
        int sb = (bi < NANCH) ? bi : 0;
        s_l4[tid] = make_float4(tx - (float)ti, ty - (float)tj,
                                logf(tw / c_RW[sb] + 1e-16f),
                                logf(th / c_RH[sb] + 1e-16f));
        s_lt[tid] = 2.0f - tw*th*(1.0f/(float)(FS*FS));
    }
    __syncthreads();

    if (tid < NLAB){
        int idx = s_idx[tid];
        if (idx >= 0)
            for (int j = tid+1; j < NLAB; j++) if (s_idx[j] == idx) { idx = -1; break; }
        s_fidx[tid] = idx;
    }

    // fragment coordinates
    int lane = tid & 31, warp = tid >> 5;
    int qr = lane >> 2;        // 0..7
    int qc = lane & 3;         // 0..3
    int pxw = warp << 5;       // warp's 32-pixel base

    // acc[T*8 + H*4 + r]: tile T (16 px), n-half H (8 outputs), mma reg r
    float acc[16];
    #pragma unroll
    for (int T = 0; T < 2; T++)
        #pragma unroll
        for (int H = 0; H < 2; H++)
            #pragma unroll
            for (int r = 0; r < 4; r++)
                acc[T*8 + H*4 + r] = s_bias[H*8 + 2*qc + (r & 1)];

    // mainloop: 32 K-steps of 8 channels, 3-ring cp.async, 1 barrier/stage
    #pragma unroll 1
    for (int s = 0; s < 32; s++){
        if (s < 31) cpwait<1>(); else cpwait<0>();
        __syncthreads();
        if (s + 2 < 32){ issue_stage(s + 2, (s + 2) % NBUF); cpcommit(); }
        const float* X = Xbuf + (s % NBUF)*(8*XPITCH);
        const float* wb = WB + (s*8)*16;
        // B fragments: b0 (c=qc, s=qr), b1 (c=qc+4, s=qr); half1 cols +8
        unsigned bh00 = __float_as_uint(wb[ qc     *16 + qr    ]);
        unsigned bh01 = __float_as_uint(wb[(qc+4)  *16 + qr    ]);
        unsigned bh10 = __float_as_uint(wb[ qc     *16 + qr + 8]);
        unsigned bh11 = __float_as_uint(wb[(qc+4)  *16 + qr + 8]);
        #pragma unroll
        for (int T = 0; T < 2; T++){
            int px = pxw + T*16 + qr;
            unsigned a0 = __float_as_uint(X[ qc   *XPITCH + px    ]);
            unsigned a1 = __float_as_uint(X[ qc   *XPITCH + px + 8]);
            unsigned a2 = __float_as_uint(X[(qc+4)*XPITCH + px    ]);
            unsigned a3 = __float_as_uint(X[(qc+4)*XPITCH + px + 8]);
            mma_tf32(acc[T*8+0], acc[T*8+1], acc[T*8+2], acc[T*8+3], a0,a1,a2,a3, bh00,bh01);
            mma_tf32(acc[T*8+4], acc[T*8+5], acc[T*8+6], acc[T*8+7], a0,a1,a2,a3, bh10,bh11);
        }
    }

    // transpose acc -> pixel-major via smem (reuse Xbuf)
    __syncthreads();                       // all stage reads done; safe to overwrite
    float* P = Xbuf;                       // 256 x PPITCH
    #pragma unroll
    for (int T = 0; T < 2; T++)
        #pragma unroll
        for (int H = 0; H < 2; H++)
            #pragma unroll
            for (int r = 0; r < 4; r++){
                int px = pxw + T*16 + qr + ((r >> 1) << 3);
                int sc = H*8 + 2*qc + (r & 1);
                P[px*PPITCH + sc] = acc[T*8 + H*4 + r];
            }
    __syncthreads();

    float o[15];
    #pragma unroll
    for (int j = 0; j < 15; j++) o[j] = P[tid*PPITCH + j];

    float lxy = 0.0f, lwh = 0.0f, lobj = 0.0f;
    pixel_losses(o, pix0 + tid, s_tb, s_ta, s_fidx, s_l4, s_lt, lxy, lwh, lobj);

    lxy = warpsum(lxy); lwh = warpsum(lwh); lobj = warpsum(lobj);
    if (lane == 0){ s_red[warp][0] = lxy; s_red[warp][1] = lwh; s_red[warp][2] = lobj; }
    __syncthreads();
    if (tid == 0){
        float vx=0.f, vw=0.f, vo=0.f;
        #pragma unroll
        for (int q = 0; q < 8; q++){ vx += s_red[q][0]; vw += s_red[q][1]; vo += s_red[q][2]; }
        g_part[blockIdx.x] = make_float4(vx, vw, vo, 0.f);
    }
}

// ---------------- finalize: reduce per-block partials ----------------
__global__ __launch_bounds__(128) void k_final(float* __restrict__ out){
    int w = threadIdx.x >> 5, lane = threadIdx.x & 31;
    const float* P = (const float*)g_part;
    double s = 0.0;
    for (int i = lane; i < TOTBLK; i += 32) s += (double)P[i*4 + w];
    #pragma unroll
    for (int o = 16; o; o >>= 1) s += __shfl_down_sync(0xffffffffu, s, o);
    __shared__ double sr[4];
    if (lane == 0) sr[w] = s;
    __syncthreads();
    if (threadIdx.x == 0){
        double xy = sr[0], wh = sr[1], obj = sr[2], cls = sr[3];
        out[0] = (float)(xy + wh + obj + cls);
        out[1] = (float)xy;
        out[2] = (float)wh;
        out[3] = (float)obj;
        out[4] = (float)cls;
    }
}

extern "C" void kernel_launch(void* const* d_in, const int* in_sizes, int n_in,
                              void* d_out, int out_size){
    const float* xin    = (const float*)d_in[0];
    const float* labels = (const float*)d_in[1];
    const float* conv_w = (const float*)d_in[2];
    const float* conv_b = (const float*)d_in[3];
    float* out = (float*)d_out;

    k_fused<<<TOTBLK, 256>>>(xin, labels, conv_w, conv_b);
    k_final<<<1, 128>>>(out);
}

// round 16
// speedup vs baseline: 2.0901x; 1.4723x over previous
#include <cuda_runtime.h>
#include <math.h>

#define NBATCH 16
#define NANCH  3
#define FS     64
#define NPIX   4096
#define NLAB   50
#define NCLS   80
#define NCH    85
#define CONVBLK 256                 // conv blocks FIRST: blockIdx 0..255, 256 px each
#define CLSBLK (NBATCH*NLAB)        // 800 class-loss blocks after
#define TOTBLK (CONVBLK + CLSBLK)   // 1056
#define NBUF   3                    // cp.async ring depth
#define XPITCH 264                  // stage pitch (floats): conflict-free A-frag loads
#define PPITCH 17                   // transpose pitch

// ---------------- device scratch ----------------
__device__ float4 g_part[TOTBLK];   // per-block partials: x=xy y=wh z=obj w=cls

__constant__ float c_RW[9] = {1.25f,2.0f,4.125f,3.75f,7.75f,7.375f,14.5f,19.5f,46.625f};
__constant__ float c_RH[9] = {1.625f,3.75f,2.875f,7.625f,5.625f,14.875f,11.25f,24.75f,40.75f};

__device__ __forceinline__ float sigm(float x){ return 1.0f/(1.0f + expf(-x)); }

// softplus(o) = max(o,0)+log1p(exp(-|o|));  BCE(sigmoid(o),t) = sp(o) - t*o
__device__ __forceinline__ float sp(float o){
    return fmaxf(o, 0.0f) + log1pf(expf(-fabsf(o)));
}

__device__ __forceinline__ float warpsum(float v){
    #pragma unroll
    for (int o = 16; o; o >>= 1) v += __shfl_down_sync(0xffffffffu, v, o);
    return v;
}

// tf32 round-to-nearest conversion (result stored as float bit-pattern)
__device__ __forceinline__ float f2tf32(float f){
    unsigned int r;
    asm("cvt.rna.tf32.f32 %0, %1;" : "=r"(r) : "f"(f));
    return __uint_as_float(r);
}

// warp-level tensor-core mma: D(16x8) += A(16x8) * B(8x8), tf32 in, fp32 acc
__device__ __forceinline__ void mma_tf32(float& c0, float& c1, float& c2, float& c3,
                                         unsigned a0, unsigned a1, unsigned a2, unsigned a3,
                                         unsigned b0, unsigned b1){
    asm volatile("mma.sync.aligned.m16n8k8.row.col.f32.tf32.tf32.f32 "
                 "{%0,%1,%2,%3}, {%4,%5,%6,%7}, {%8,%9}, {%0,%1,%2,%3};"
                 : "+f"(c0), "+f"(c1), "+f"(c2), "+f"(c3)
                 : "r"(a0), "r"(a1), "r"(a2), "r"(a3), "r"(b0), "r"(b1));
}

// cp.async helpers (Ampere+)
__device__ __forceinline__ void cpa16(unsigned int saddr, const float* g){
    asm volatile("cp.async.cg.shared.global [%0], [%1], 16;" :: "r"(saddr), "l"(g));
}
__device__ __forceinline__ void cpcommit(){ asm volatile("cp.async.commit_group;" ::: "memory"); }
template<int N> __device__ __forceinline__ void cpwait(){
    asm volatile("cp.async.wait_group %0;" :: "n"(N) : "memory");
}

// candidate cell index for one label (or -1)
__device__ __forceinline__ int label_idx(const float* __restrict__ L,
                                         float& tx, float& ty, float& tw, float& th,
                                         int& bi){
    float cls = L[0], x = L[1], y = L[2], w = L[3], h = L[4];
    tx = x*FS; ty = y*FS; tw = w*FS; th = h*FS;
    float best = -1e30f; bi = 0;
    #pragma unroll
    for (int n = 0; n < 9; n++){
        float inter = fminf(tw, c_RW[n]) * fminf(th, c_RH[n]);
        float uni   = tw*th + c_RW[n]*c_RH[n] - inter;
        float iou   = inter/uni;
        if (iou > best){ best = iou; bi = n; }
    }
    bool valid = (cls + x + y + w + h) > 0.0f;
    if (!(valid && bi < NANCH)) return -1;
    int ti = (int)tx, tj = (int)ty;
    return (bi<<12)|(tj<<6)|ti;
}

// ---------------- fused kernel: 256 conv (tf32 MMA) + 800 cls blocks ----------------
__global__ __launch_bounds__(256, 4) void k_fused(const float* __restrict__ xin,
                                                  const float* __restrict__ labels,
                                                  const float* __restrict__ conv_w,
                                                  const float* __restrict__ conv_b){
    __shared__ __align__(16) float Xbuf[NBUF*8*XPITCH];   // 25344 B (stages / transpose / cls xs)
    __shared__ __align__(16) float WB[256*16];            // tf32 weights [c][s], 16 KB
    __shared__ float4 s_tb[NLAB];
    __shared__ float  s_ta[NLAB];
    __shared__ int    s_idx[NLAB];
    __shared__ int    s_fidx[NLAB];
    __shared__ float4 s_l4[NLAB];
    __shared__ float  s_lt[NLAB];
    __shared__ float  s_bias[16];
    __shared__ float  s_red[8][3];
    __shared__ float  s_wred[8];
    __shared__ int    s_win;
    __shared__ int    s_cand[NLAB];
    __shared__ int    s_match[NLAB];
    __shared__ int    s_ncand, s_nmatch;

    int tid = threadIdx.x;

    if (blockIdx.x >= CONVBLK){
        // ================= class-loss block for label (b, k) =================
        int mb = (int)blockIdx.x - CONVBLK;
        int b  = mb / NLAB, k = mb - b*NLAB;
        float* xs = Xbuf;

        if (tid < NLAB){
            float tx,ty,tw,th; int bi;
            s_idx[tid] = label_idx(labels + (size_t)(b*NLAB + tid)*5, tx,ty,tw,th, bi);
        }
        __syncthreads();
        if (tid == 0){
            int idx = s_idx[k];
            if (idx >= 0)
                for (int j = k+1; j < NLAB; j++) if (s_idx[j] == idx) { idx = -1; break; }
            s_win = idx;
        }
        __syncthreads();
        int idx = s_win;
        if (idx < 0){
            if (tid == 0) g_part[blockIdx.x] = make_float4(0.f,0.f,0.f,0.f);
            return;
        }
        int a = idx >> 12, pix = idx & 4095;
        int cls = (int)labels[(size_t)(b*NLAB + k)*5];

        xs[tid] = __ldg(xin + ((size_t)(b*256 + tid))*NPIX + pix);
        __syncthreads();

        int w = tid >> 5, lane = tid & 31;   // 8 warps x 10 classes = 80
        float lc = 0.0f;
        #pragma unroll 2
        for (int t = 0; t < 10; t++){
            int c = w + (t<<3);
            int o = a*NCH + 5 + c;
            const float* wr = conv_w + (size_t)o*256;
            float s = 0.0f;
            #pragma unroll
            for (int i = 0; i < 8; i++) s += xs[lane + (i<<5)]*__ldg(wr + lane + (i<<5));
            s = warpsum(s);
            if (lane == 0){
                s += conv_b[o];
                lc += sp(s) - ((c == cls) ? s : 0.0f);
            }
        }
        if (lane == 0) s_wred[w] = lc;
        __syncthreads();
        if (tid == 0){
            float v = 0.0f;
            #pragma unroll
            for (int q = 0; q < 8; q++) v += s_wred[q];
            g_part[blockIdx.x] = make_float4(0.f, 0.f, 0.f, v);
        }
        return;
    }

    // ================= conv block: 256 px, tf32 MMA, per-warp pipeline =================
    int cb   = (int)blockIdx.x;
    int b    = cb >> 4;
    int pix0 = (cb & 15) << 8;
    int lane = tid & 31, warp = tid >> 5;
    int qr = lane >> 2;        // 0..7
    int qc = lane & 3;         // 0..3
    int pxw = warp << 5;       // warp's 32-pixel base

    const float* xgb = xin + (size_t)b*256*NPIX + pix0;
    unsigned int sx0 = (unsigned int)__cvta_generic_to_shared(&Xbuf[0]);

    // per-warp staging: warp stages ONLY its own 32 pixels x 8 channels (2x16B/thread)
    auto issue_stage = [&](int q, int buf){
        unsigned int sb = sx0 + (unsigned int)(buf*(8*XPITCH*4));
        #pragma unroll
        for (int j = 0; j < 2; j++){
            int u  = lane + (j << 5);          // 0..63
            int c  = u >> 3;                   // 0..7
            int px = pxw + ((u & 7) << 2);     // 4-px chunk within warp window
            cpa16(sb + (unsigned int)((c*XPITCH + px) << 2),
                  xgb + (size_t)(q*8 + c)*NPIX + px);
        }
    };
    issue_stage(0, 0); cpcommit();
    issue_stage(1, 1); cpcommit();

    // weights -> smem as tf32, layout WB[c*16 + s]
    for (int i = tid; i < 15*256; i += 256){
        int s = i >> 8, c = i & 255;
        int a = s/5, j = s - a*5;
        WB[c*16 + s] = f2tf32(conv_w[(a*NCH + j)*256 + c]);
    }
    WB[tid*16 + 15] = 0.0f;
    if (tid >= 224 && tid < 239){ int s = tid-224; int a = s/5; s_bias[s] = conv_b[a*NCH + (s - a*5)]; }
    if (tid == 239) s_bias[15] = 0.0f;
    if (tid == 240){ s_ncand = 0; s_nmatch = 0; }

    float tly = 0.f, bry = -1.f;               // this thread's truth y-range (tid<50)
    if (tid < NLAB){
        const float* L = labels + (size_t)(b*NLAB + tid)*5;
        float tx,ty,tw,th; int bi;
        int idx = label_idx(L, tx,ty,tw,th, bi);
        s_idx[tid] = idx;
        tly = ty - th*0.5f; bry = ty + th*0.5f;
        s_tb[tid]  = make_float4(tx - tw*0.5f, tly, tx + tw*0.5f, bry);
        s_ta[tid]  = tw*th;
        int ti = (int)tx, tj = (int)ty;
        int sb = (bi < NANCH) ? bi : 0;
        s_l4[tid] = make_float4(tx - (float)ti, ty - (float)tj,
                                logf(tw / c_RW[sb] + 1e-16f),
                                logf(th / c_RH[sb] + 1e-16f));
        s_lt[tid] = 2.0f - tw*th*(1.0f/(float)(FS*FS));
    }
    __syncthreads();

    // phase2: winner selection + candidate/match lists (order-independent appends)
    float r0f = (float)(pix0 >> 6);            // first image row of this strip
    if (tid < NLAB){
        int idx = s_idx[tid];
        if (idx >= 0)
            for (int j = tid+1; j < NLAB; j++) if (s_idx[j] == idx) { idx = -1; break; }
        s_fidx[tid] = idx;
        // truth can ignore only pixels whose center lies inside it (proven exact);
        // block covers rows [r0, r0+4)
        if (bry >= r0f && tly <= r0f + 4.0f){
            int s = atomicAdd(&s_ncand, 1);
            s_cand[s] = tid;
        }
        if (idx >= 0){
            unsigned rel = (unsigned)((idx & 4095) - pix0);
            if (rel < 256u){
                int s = atomicAdd(&s_nmatch, 1);
                s_match[s] = (tid << 14) | idx;
            }
        }
    }

    // acc[T*8 + H*4 + r]: tile T (16 px), n-half H (8 outputs), mma reg r
    float acc[16];
    #pragma unroll
    for (int T = 0; T < 2; T++)
        #pragma unroll
        for (int H = 0; H < 2; H++)
            #pragma unroll
            for (int r = 0; r < 4; r++)
                acc[T*8 + H*4 + r] = s_bias[H*8 + 2*qc + (r & 1)];

    // mainloop: 32 K-steps of 8 channels; per-warp ring -> NO block barriers
    #pragma unroll 1
    for (int s = 0; s < 32; s++){
        if (s < 31) cpwait<1>(); else cpwait<0>();
        __syncwarp();
        if (s + 2 < 32){ issue_stage(s + 2, (s + 2) % NBUF); cpcommit(); }
        const float* X = Xbuf + (s % NBUF)*(8*XPITCH);
        const float* wb = WB + (s*8)*16;
        unsigned bh00 = __float_as_uint(wb[ qc     *16 + qr    ]);
        unsigned bh01 = __float_as_uint(wb[(qc+4)  *16 + qr    ]);
        unsigned bh10 = __float_as_uint(wb[ qc     *16 + qr + 8]);
        unsigned bh11 = __float_as_uint(wb[(qc+4)  *16 + qr + 8]);
        #pragma unroll
        for (int T = 0; T < 2; T++){
            int px = pxw + T*16 + qr;
            unsigned a0 = __float_as_uint(X[ qc   *XPITCH + px    ]);
            unsigned a1 = __float_as_uint(X[ qc   *XPITCH + px + 8]);
            unsigned a2 = __float_as_uint(X[(qc+4)*XPITCH + px    ]);
            unsigned a3 = __float_as_uint(X[(qc+4)*XPITCH + px + 8]);
            mma_tf32(acc[T*8+0], acc[T*8+1], acc[T*8+2], acc[T*8+3], a0,a1,a2,a3, bh00,bh01);
            mma_tf32(acc[T*8+4], acc[T*8+5], acc[T*8+6], acc[T*8+7], a0,a1,a2,a3, bh10,bh11);
        }
    }

    // transpose acc -> pixel-major via smem (reuse Xbuf; full barrier: other warps
    // may still be reading their stage buffers)
    __syncthreads();
    float* P = Xbuf;                       // 256 x PPITCH
    #pragma unroll
    for (int T = 0; T < 2; T++)
        #pragma unroll
        for (int H = 0; H < 2; H++)
            #pragma unroll
            for (int r = 0; r < 4; r++){
                int px = pxw + T*16 + qr + ((r >> 1) << 3);
                int sc = H*8 + 2*qc + (r & 1);
                P[px*PPITCH + sc] = acc[T*8 + H*4 + r];
            }
    __syncwarp();                          // per-warp region -> warp sync suffices

    float o[15];
    #pragma unroll
    for (int j = 0; j < 15; j++) o[j] = P[(pxw + lane)*PPITCH + j];

    // ---------------- per-pixel losses with pruned lists ----------------
    int pix = pix0 + pxw + lane;
    const float MAW[3] = {1.25f, 2.0f, 4.125f};
    const float MAH[3] = {1.625f, 3.75f, 2.875f};
    float fw = (float)(pix & 63);
    float fh = (float)(pix >> 6);
    float ax0[3], ay0[3], ax1[3], ay1[3], areaA[3];
    #pragma unroll
    for (int a = 0; a < 3; a++){
        float o0 = o[a*5+0], o1 = o[a*5+1];
        float o2 = o[a*5+2], o3 = o[a*5+3];
        float pw = expf(o2)*MAW[a], ph = expf(o3)*MAH[a];
        float px = sigm(o0) + fw, py = sigm(o1) + fh;
        areaA[a] = pw*ph;
        ax0[a] = px - pw*0.5f; ay0[a] = py - ph*0.5f;
        ax1[a] = px + pw*0.5f; ay1[a] = py + ph*0.5f;
    }
    int ign = 0;
    int nc = s_ncand;
    for (int j = 0; j < nc; j++){
        int kk = s_cand[j];
        float4 t = s_tb[kk];
        float ta = s_ta[kk];
        #pragma unroll
        for (int a = 0; a < 3; a++){
            float iw = fmaxf(fminf(ax1[a], t.z) - fmaxf(ax0[a], t.x), 0.0f);
            float ih = fmaxf(fminf(ay1[a], t.w) - fmaxf(ay0[a], t.y), 0.0f);
            float inter = iw*ih;
            float den   = areaA[a] + ta - inter;
            ign |= (inter > 0.7f*den) << a;
        }
    }
    int msl[3] = {-1,-1,-1};
    int nm = s_nmatch;
    for (int j = 0; j < nm; j++){
        int pk = s_match[j];
        int e  = pk & 16383;
        if ((e & 4095) == pix) msl[e >> 12] = pk >> 14;
    }

    float lxy = 0.0f, lwh = 0.0f, lobj = 0.0f;
    #pragma unroll
    for (int a = 0; a < 3; a++){
        float o4 = o[a*5+4];
        int slot = msl[a];
        if (slot >= 0){
            lobj += sp(o4) - o4;
            float4 d = s_l4[slot];
            float ts = s_lt[slot];
            float oa = o[a*5+0], ob = o[a*5+1];
            lxy += (sp(oa) - d.x*oa + sp(ob) - d.y*ob)*ts;
            float dw = o[a*5+2] - d.z, dh = o[a*5+3] - d.w;
            lwh += (dw*dw + dh*dh)*0.5f*ts;
        } else if (!((ign >> a) & 1)){
            lobj += sp(o4);
        }
    }

    lxy = warpsum(lxy); lwh = warpsum(lwh); lobj = warpsum(lobj);
    if (lane == 0){ s_red[warp][0] = lxy; s_red[warp][1] = lwh; s_red[warp][2] = lobj; }
    __syncthreads();
    if (tid == 0){
        float vx=0.f, vw=0.f, vo=0.f;
        #pragma unroll
        for (int q = 0; q < 8; q++){ vx += s_red[q][0]; vw += s_red[q][1]; vo += s_red[q][2]; }
        g_part[blockIdx.x] = make_float4(vx, vw, vo, 0.f);
    }
}

// ---------------- finalize: reduce per-block partials ----------------
__global__ __launch_bounds__(128) void k_final(float* __restrict__ out){
    int w = threadIdx.x >> 5, lane = threadIdx.x & 31;
    const float* P = (const float*)g_part;
    double s = 0.0;
    for (int i = lane; i < TOTBLK; i += 32) s += (double)P[i*4 + w];
    #pragma unroll
    for (int o = 16; o; o >>= 1) s += __shfl_down_sync(0xffffffffu, s, o);
    __shared__ double sr[4];
    if (lane == 0) sr[w] = s;
    __syncthreads();
    if (threadIdx.x == 0){
        double xy = sr[0], wh = sr[1], obj = sr[2], cls = sr[3];
        out[0] = (float)(xy + wh + obj + cls);
        out[1] = (float)xy;
        out[2] = (float)wh;
        out[3] = (float)obj;
        out[4] = (float)cls;
    }
}

extern "C" void kernel_launch(void* const* d_in, const int* in_sizes, int n_in,
                              void* d_out, int out_size){
    const float* xin    = (const float*)d_in[0];
    const float* labels = (const float*)d_in[1];
    const float* conv_w = (const float*)d_in[2];
    const float* conv_b = (const float*)d_in[3];
    float* out = (float*)d_out;

    k_fused<<<TOTBLK, 256>>>(xin, labels, conv_w, conv_b);
    k_final<<<1, 128>>>(out);
}

// round 17
// speedup vs baseline: 2.1460x; 1.0268x over previous
#include <cuda_runtime.h>
#include <math.h>

#define NBATCH 16
#define NANCH  3
#define FS     64
#define NPIX   4096
#define NLAB   50
#define NCLS   80
#define NCH    85
#define CONVBLK 256                 // conv blocks FIRST: blockIdx 0..255, 256 px each
#define CLSBLK (NBATCH*NLAB)        // 800 class-loss blocks after
#define TOTBLK (CONVBLK + CLSBLK)   // 1056
#define NBUF   3                    // cp.async ring depth
#define XPITCH 264                  // stage pitch (floats): conflict-free A-frag loads
#define PPITCH 17                   // transpose pitch

// ---------------- device scratch ----------------
__device__ double       g_acc[4];     // xy, wh, obj, cls (zero-init; reset by last block)
__device__ unsigned int g_tick;       // ticket (zero-init; reset by last block)

__constant__ float c_RW[9] = {1.25f,2.0f,4.125f,3.75f,7.75f,7.375f,14.5f,19.5f,46.625f};
__constant__ float c_RH[9] = {1.625f,3.75f,2.875f,7.625f,5.625f,14.875f,11.25f,24.75f,40.75f};

__device__ __forceinline__ float sigm(float x){ return 1.0f/(1.0f + expf(-x)); }

// softplus(o) = max(o,0)+log1p(exp(-|o|));  BCE(sigmoid(o),t) = sp(o) - t*o
__device__ __forceinline__ float sp(float o){
    return fmaxf(o, 0.0f) + log1pf(expf(-fabsf(o)));
}

__device__ __forceinline__ float warpsum(float v){
    #pragma unroll
    for (int o = 16; o; o >>= 1) v += __shfl_down_sync(0xffffffffu, v, o);
    return v;
}

// tf32 round-to-nearest conversion (result stored as float bit-pattern)
__device__ __forceinline__ float f2tf32(float f){
    unsigned int r;
    asm("cvt.rna.tf32.f32 %0, %1;" : "=r"(r) : "f"(f));
    return __uint_as_float(r);
}

// warp-level tensor-core mma: D(16x8) += A(16x8) * B(8x8), tf32 in, fp32 acc
__device__ __forceinline__ void mma_tf32(float& c0, float& c1, float& c2, float& c3,
                                         unsigned a0, unsigned a1, unsigned a2, unsigned a3,
                                         unsigned b0, unsigned b1){
    asm volatile("mma.sync.aligned.m16n8k8.row.col.f32.tf32.tf32.f32 "
                 "{%0,%1,%2,%3}, {%4,%5,%6,%7}, {%8,%9}, {%0,%1,%2,%3};"
                 : "+f"(c0), "+f"(c1), "+f"(c2), "+f"(c3)
                 : "r"(a0), "r"(a1), "r"(a2), "r"(a3), "r"(b0), "r"(b1));
}

// cp.async helpers (Ampere+)
__device__ __forceinline__ void cpa16(unsigned int saddr, const float* g){
    asm volatile("cp.async.cg.shared.global [%0], [%1], 16;" :: "r"(saddr), "l"(g));
}
__device__ __forceinline__ void cpcommit(){ asm volatile("cp.async.commit_group;" ::: "memory"); }
template<int N> __device__ __forceinline__ void cpwait(){
    asm volatile("cp.async.wait_group %0;" :: "n"(N) : "memory");
}

// candidate cell index for one label (or -1)
__device__ __forceinline__ int label_idx(const float* __restrict__ L,
                                         float& tx, float& ty, float& tw, float& th,
                                         int& bi){
    float cls = L[0], x = L[1], y = L[2], w = L[3], h = L[4];
    tx = x*FS; ty = y*FS; tw = w*FS; th = h*FS;
    float best = -1e30f; bi = 0;
    #pragma unroll
    for (int n = 0; n < 9; n++){
        float inter = fminf(tw, c_RW[n]) * fminf(th, c_RH[n]);
        float uni   = tw*th + c_RW[n]*c_RH[n] - inter;
        float iou   = inter/uni;
        if (iou > best){ best = iou; bi = n; }
    }
    bool valid = (cls + x + y + w + h) > 0.0f;
    if (!(valid && bi < NANCH)) return -1;
    int ti = (int)tx, tj = (int)ty;
    return (bi<<12)|(tj<<6)|ti;
}

// block tail: tid 0 publishes partial, takes ticket; last block writes out + resets
__device__ __forceinline__ void block_tail(int tid, float vx, float vw, float vo, float vc,
                                           float* __restrict__ out){
    if (tid != 0) return;
    if (vx != 0.f) atomicAdd(&g_acc[0], (double)vx);
    if (vw != 0.f) atomicAdd(&g_acc[1], (double)vw);
    if (vo != 0.f) atomicAdd(&g_acc[2], (double)vo);
    if (vc != 0.f) atomicAdd(&g_acc[3], (double)vc);
    __threadfence();
    unsigned int t = atomicAdd(&g_tick, 1u);
    if (t == TOTBLK - 1u){
        // read via L2 atomics (bypasses L1), then write out and reset for next replay
        double xy  = atomicAdd(&g_acc[0], 0.0);
        double wh  = atomicAdd(&g_acc[1], 0.0);
        double obj = atomicAdd(&g_acc[2], 0.0);
        double cls = atomicAdd(&g_acc[3], 0.0);
        out[0] = (float)(xy + wh + obj + cls);
        out[1] = (float)xy;
        out[2] = (float)wh;
        out[3] = (float)obj;
        out[4] = (float)cls;
        __threadfence();
        atomicExch((unsigned long long*)&g_acc[0], 0ull);
        atomicExch((unsigned long long*)&g_acc[1], 0ull);
        atomicExch((unsigned long long*)&g_acc[2], 0ull);
        atomicExch((unsigned long long*)&g_acc[3], 0ull);
        __threadfence();
        atomicExch(&g_tick, 0u);
    }
}

// ---------------- fused kernel: 256 conv (tf32 MMA) + 800 cls blocks ----------------
__global__ __launch_bounds__(256, 4) void k_fused(const float* __restrict__ xin,
                                                  const float* __restrict__ labels,
                                                  const float* __restrict__ conv_w,
                                                  const float* __restrict__ conv_b,
                                                  float* __restrict__ out){
    __shared__ __align__(16) float Xbuf[NBUF*8*XPITCH];   // 25344 B (stages / transpose / cls xs)
    __shared__ __align__(16) float WB[256*16];            // tf32 weights [c][s], 16 KB
    __shared__ float4 s_tb[NLAB];
    __shared__ float  s_ta[NLAB];
    __shared__ int    s_idx[NLAB];
    __shared__ float4 s_l4[NLAB];
    __shared__ float  s_lt[NLAB];
    __shared__ float  s_bias[16];
    __shared__ float  s_red[8][3];
    __shared__ float  s_wred[8];
    __shared__ int    s_win;
    __shared__ int    s_cand[NLAB];
    __shared__ int    s_match[NLAB];
    __shared__ int    s_ncand, s_nmatch;

    int tid = threadIdx.x;

    if (blockIdx.x >= CONVBLK){
        // ================= class-loss block for label (b, k) =================
        int mb = (int)blockIdx.x - CONVBLK;
        int b  = mb / NLAB, k = mb - b*NLAB;
        float* xs = Xbuf;

        if (tid < NLAB){
            float tx,ty,tw,th; int bi;
            s_idx[tid] = label_idx(labels + (size_t)(b*NLAB + tid)*5, tx,ty,tw,th, bi);
        }
        __syncthreads();
        if (tid == 0){
            int idx = s_idx[k];
            if (idx >= 0)
                for (int j = k+1; j < NLAB; j++) if (s_idx[j] == idx) { idx = -1; break; }
            s_win = idx;
        }
        __syncthreads();
        int idx = s_win;
        if (idx < 0){
            block_tail(tid, 0.f, 0.f, 0.f, 0.f, out);
            return;
        }
        int a = idx >> 12, pix = idx & 4095;
        int cls = (int)labels[(size_t)(b*NLAB + k)*5];

        xs[tid] = __ldg(xin + ((size_t)(b*256 + tid))*NPIX + pix);
        __syncthreads();

        int w = tid >> 5, lane = tid & 31;   // 8 warps x 10 classes = 80
        float lc = 0.0f;
        #pragma unroll 2
        for (int t = 0; t < 10; t++){
            int c = w + (t<<3);
            int o = a*NCH + 5 + c;
            const float* wr = conv_w + (size_t)o*256;
            float s = 0.0f;
            #pragma unroll
            for (int i = 0; i < 8; i++) s += xs[lane + (i<<5)]*__ldg(wr + lane + (i<<5));
            s = warpsum(s);
            if (lane == 0){
                s += conv_b[o];
                lc += sp(s) - ((c == cls) ? s : 0.0f);
            }
        }
        if (lane == 0) s_wred[w] = lc;
        __syncthreads();
        float v = 0.0f;
        if (tid == 0){
            #pragma unroll
            for (int q = 0; q < 8; q++) v += s_wred[q];
        }
        block_tail(tid, 0.f, 0.f, 0.f, v, out);
        return;
    }

    // ================= conv block: 256 px, tf32 MMA, per-warp pipeline =================
    int cb   = (int)blockIdx.x;
    int b    = cb >> 4;
    int pix0 = (cb & 15) << 8;
    int lane = tid & 31, warp = tid >> 5;
    int qr = lane >> 2;        // 0..7
    int qc = lane & 3;         // 0..3
    int pxw = warp << 5;       // warp's 32-pixel base

    const float* xgb = xin + (size_t)b*256*NPIX + pix0;
    unsigned int sx0 = (unsigned int)__cvta_generic_to_shared(&Xbuf[0]);

    // per-warp staging: warp stages ONLY its own 32 pixels x 8 channels (2x16B/thread)
    auto issue_stage = [&](int q, int buf){
        unsigned int sb = sx0 + (unsigned int)(buf*(8*XPITCH*4));
        #pragma unroll
        for (int j = 0; j < 2; j++){
            int u  = lane + (j << 5);          // 0..63
            int c  = u >> 3;                   // 0..7
            int px = pxw + ((u & 7) << 2);     // 4-px chunk within warp window
            cpa16(sb + (unsigned int)((c*XPITCH + px) << 2),
                  xgb + (size_t)(q*8 + c)*NPIX + px);
        }
    };
    issue_stage(0, 0); cpcommit();
    issue_stage(1, 1); cpcommit();

    // weights -> smem as tf32, layout WB[c*16 + s]
    for (int i = tid; i < 15*256; i += 256){
        int s = i >> 8, c = i & 255;
        int a = s/5, j = s - a*5;
        WB[c*16 + s] = f2tf32(conv_w[(a*NCH + j)*256 + c]);
    }
    WB[tid*16 + 15] = 0.0f;
    if (tid >= 224 && tid < 239){ int s = tid-224; int a = s/5; s_bias[s] = conv_b[a*NCH + (s - a*5)]; }
    if (tid == 239) s_bias[15] = 0.0f;
    if (tid == 240){ s_ncand = 0; s_nmatch = 0; }

    float tly = 0.f, bry = -1.f;               // this thread's truth y-range (tid<50)
    if (tid < NLAB){
        const float* L = labels + (size_t)(b*NLAB + tid)*5;
        float tx,ty,tw,th; int bi;
        int idx = label_idx(L, tx,ty,tw,th, bi);
        s_idx[tid] = idx;
        tly = ty - th*0.5f; bry = ty + th*0.5f;
        s_tb[tid]  = make_float4(tx - tw*0.5f, tly, tx + tw*0.5f, bry);
        s_ta[tid]  = tw*th;
        int ti = (int)tx, tj = (int)ty;
        int sb = (bi < NANCH) ? bi : 0;
        s_l4[tid] = make_float4(tx - (float)ti, ty - (float)tj,
                                logf(tw / c_RW[sb] + 1e-16f),
                                logf(th / c_RH[sb] + 1e-16f));
        s_lt[tid] = 2.0f - tw*th*(1.0f/(float)(FS*FS));
    }
    __syncthreads();

    // phase2: winner selection + candidate/match lists (order-independent appends)
    float r0f = (float)(pix0 >> 6);            // first image row of this strip
    if (tid < NLAB){
        int idx = s_idx[tid];
        if (idx >= 0)
            for (int j = tid+1; j < NLAB; j++) if (s_idx[j] == idx) { idx = -1; break; }
        // truth can ignore only pixels whose center lies inside it (proven exact);
        // block covers rows [r0, r0+4)
        if (bry >= r0f && tly <= r0f + 4.0f){
            int s = atomicAdd(&s_ncand, 1);
            s_cand[s] = tid;
        }
        if (idx >= 0){
            unsigned rel = (unsigned)((idx & 4095) - pix0);
            if (rel < 256u){
                int s = atomicAdd(&s_nmatch, 1);
                s_match[s] = (tid << 14) | idx;
            }
        }
    }

    // acc[T*8 + H*4 + r]: tile T (16 px), n-half H (8 outputs), mma reg r
    float acc[16];
    #pragma unroll
    for (int T = 0; T < 2; T++)
        #pragma unroll
        for (int H = 0; H < 2; H++)
            #pragma unroll
            for (int r = 0; r < 4; r++)
                acc[T*8 + H*4 + r] = s_bias[H*8 + 2*qc + (r & 1)];

    // mainloop: 32 K-steps of 8 channels; per-warp ring -> NO block barriers
    #pragma unroll 1
    for (int s = 0; s < 32; s++){
        if (s < 31) cpwait<1>(); else cpwait<0>();
        __syncwarp();
        if (s + 2 < 32){ issue_stage(s + 2, (s + 2) % NBUF); cpcommit(); }
        const float* X = Xbuf + (s % NBUF)*(8*XPITCH);
        const float* wb = WB + (s*8)*16;
        unsigned bh00 = __float_as_uint(wb[ qc     *16 + qr    ]);
        unsigned bh01 = __float_as_uint(wb[(qc+4)  *16 + qr    ]);
        unsigned bh10 = __float_as_uint(wb[ qc     *16 + qr + 8]);
        unsigned bh11 = __float_as_uint(wb[(qc+4)  *16 + qr + 8]);
        #pragma unroll
        for (int T = 0; T < 2; T++){
            int px = pxw + T*16 + qr;
            unsigned a0 = __float_as_uint(X[ qc   *XPITCH + px    ]);
            unsigned a1 = __float_as_uint(X[ qc   *XPITCH + px + 8]);
            unsigned a2 = __float_as_uint(X[(qc+4)*XPITCH + px    ]);
            unsigned a3 = __float_as_uint(X[(qc+4)*XPITCH + px + 8]);
            mma_tf32(acc[T*8+0], acc[T*8+1], acc[T*8+2], acc[T*8+3], a0,a1,a2,a3, bh00,bh01);
            mma_tf32(acc[T*8+4], acc[T*8+5], acc[T*8+6], acc[T*8+7], a0,a1,a2,a3, bh10,bh11);
        }
    }

    // transpose acc -> pixel-major via smem (reuse Xbuf; full barrier: other warps
    // may still be reading their stage buffers)
    __syncthreads();
    float* P = Xbuf;                       // 256 x PPITCH
    #pragma unroll
    for (int T = 0; T < 2; T++)
        #pragma unroll
        for (int H = 0; H < 2; H++)
            #pragma unroll
            for (int r = 0; r < 4; r++){
                int px = pxw + T*16 + qr + ((r >> 1) << 3);
                int sc = H*8 + 2*qc + (r & 1);
                P[px*PPITCH + sc] = acc[T*8 + H*4 + r];
            }
    __syncwarp();                          // per-warp region -> warp sync suffices

    float o[15];
    #pragma unroll
    for (int j = 0; j < 15; j++) o[j] = P[(pxw + lane)*PPITCH + j];

    // ---------------- per-pixel losses with pruned lists ----------------
    int pix = pix0 + pxw + lane;
    const float MAW[3] = {1.25f, 2.0f, 4.125f};
    const float MAH[3] = {1.625f, 3.75f, 2.875f};
    float fw = (float)(pix & 63);
    float fh = (float)(pix >> 6);
    float ax0[3], ay0[3], ax1[3], ay1[3], areaA[3];
    #pragma unroll
    for (int a = 0; a < 3; a++){
        float o0 = o[a*5+0], o1 = o[a*5+1];
        float o2 = o[a*5+2], o3 = o[a*5+3];
        float pw = expf(o2)*MAW[a], ph = expf(o3)*MAH[a];
        float px = sigm(o0) + fw, py = sigm(o1) + fh;
        areaA[a] = pw*ph;
        ax0[a] = px - pw*0.5f; ay0[a] = py - ph*0.5f;
        ax1[a] = px + pw*0.5f; ay1[a] = py + ph*0.5f;
    }
    int ign = 0;
    int nc = s_ncand;
    for (int j = 0; j < nc; j++){
        int kk = s_cand[j];
        float4 t = s_tb[kk];
        float ta = s_ta[kk];
        #pragma unroll
        for (int a = 0; a < 3; a++){
            float iw = fmaxf(fminf(ax1[a], t.z) - fmaxf(ax0[a], t.x), 0.0f);
            float ih = fmaxf(fminf(ay1[a], t.w) - fmaxf(ay0[a], t.y), 0.0f);
            float inter = iw*ih;
            float den   = areaA[a] + ta - inter;
            ign |= (inter > 0.7f*den) << a;
        }
    }
    int msl[3] = {-1,-1,-1};
    int nm = s_nmatch;
    for (int j = 0; j < nm; j++){
        int pk = s_match[j];
        int e  = pk & 16383;
        if ((e & 4095) == pix) msl[e >> 12] = pk >> 14;
    }

    float lxy = 0.0f, lwh = 0.0f, lobj = 0.0f;
    #pragma unroll
    for (int a = 0; a < 3; a++){
        float o4 = o[a*5+4];
        int slot = msl[a];
        if (slot >= 0){
            lobj += sp(o4) - o4;
            float4 d = s_l4[slot];
            float ts = s_lt[slot];
            float oa = o[a*5+0], ob = o[a*5+1];
            lxy += (sp(oa) - d.x*oa + sp(ob) - d.y*ob)*ts;
            float dw = o[a*5+2] - d.z, dh = o[a*5+3] - d.w;
            lwh += (dw*dw + dh*dh)*0.5f*ts;
        } else if (!((ign >> a) & 1)){
            lobj += sp(o4);
        }
    }

    lxy = warpsum(lxy); lwh = warpsum(lwh); lobj = warpsum(lobj);
    if (lane == 0){ s_red[warp][0] = lxy; s_red[warp][1] = lwh; s_red[warp][2] = lobj; }
    __syncthreads();
    float vx = 0.f, vw = 0.f, vo = 0.f;
    if (tid == 0){
        #pragma unroll
        for (int q = 0; q < 8; q++){ vx += s_red[q][0]; vw += s_red[q][1]; vo += s_red[q][2]; }
    }
    block_tail(tid, vx, vw, vo, 0.f, out);
}

extern "C" void kernel_launch(void* const* d_in, const int* in_sizes, int n_in,
                              void* d_out, int out_size){
    const float* xin    = (const float*)d_in[0];
    const float* labels = (const float*)d_in[1];
    const float* conv_w = (const float*)d_in[2];
    const float* conv_b = (const float*)d_in[3];
    float* out = (float*)d_out;

    k_fused<<<TOTBLK, 256>>>(xin, labels, conv_w, conv_b, out);
}